// round 1
// baseline (speedup 1.0000x reference)
#include <cuda_runtime.h>
#include <cuda_bf16.h>
#include <math.h>

// Problem constants
#define BB 128
#define NN 64
#define DD 768
#define HH 32
#define DK 24
#define LL 4
#define TE 32
#define TD 40
#define VP 512

// ---------------- scratch (device globals; no allocations allowed) -------------
__device__ float g_q[BB*HH*NN*DK];   // [b,h,n,d]
__device__ float g_k[BB*HH*NN*DK];
__device__ float g_v[BB*HH*NN*DK];
__device__ float g_pb[BB*HH*NN*NN];  // path bias [b,h,i,j]
__device__ float g_z[BB*NN*HH*DK];   // [b,n,h*dk]

// ---------------- Kernel A: QKV GEMM  X[8192,768] @ W[768,2304] -----------------
__global__ void __launch_bounds__(256) qkv_gemm_kernel(const float* __restrict__ X,
                                                       const float* __restrict__ W,
                                                       const float* __restrict__ Bq) {
    __shared__ float As[16][68];
    __shared__ float Bs[16][64];
    int tx = threadIdx.x & 15, ty = threadIdx.x >> 4;
    int m0 = blockIdx.y * 64, c0 = blockIdx.x * 64;
    float acc[4][4] = {};
    for (int k0 = 0; k0 < 768; k0 += 16) {
        #pragma unroll
        for (int it = 0; it < 4; it++) {
            int idx = threadIdx.x + it * 256;
            int m = idx >> 4, kk = idx & 15;
            As[kk][m] = X[(m0 + m) * 768 + k0 + kk];
        }
        #pragma unroll
        for (int it = 0; it < 4; it++) {
            int idx = threadIdx.x + it * 256;
            int kk = idx >> 6, c = idx & 63;
            Bs[kk][c] = W[(k0 + kk) * 2304 + c0 + c];
        }
        __syncthreads();
        #pragma unroll
        for (int kk = 0; kk < 16; kk++) {
            float4 a4 = *(const float4*)&As[kk][ty * 4];
            float4 b4 = *(const float4*)&Bs[kk][tx * 4];
            float av[4] = {a4.x, a4.y, a4.z, a4.w};
            float bv[4] = {b4.x, b4.y, b4.z, b4.w};
            #pragma unroll
            for (int ri = 0; ri < 4; ri++)
                #pragma unroll
                for (int ci = 0; ci < 4; ci++)
                    acc[ri][ci] += av[ri] * bv[ci];
        }
        __syncthreads();
    }
    #pragma unroll
    for (int ri = 0; ri < 4; ri++) {
        int m = m0 + ty * 4 + ri;
        int bb = m >> 6, n = m & 63;
        #pragma unroll
        for (int ci = 0; ci < 4; ci++) {
            int c = c0 + tx * 4 + ci;
            float val = acc[ri][ci] + Bq[c];
            int s = c / 768;
            int rem = c - s * 768;
            int h = rem / 24, d = rem % 24;
            float* dst = (s == 0) ? g_q : (s == 1) ? g_k : g_v;
            dst[(((bb * HH + h) * NN) + n) * DK + d] = val;
        }
    }
}

// ---------------- Kernel D: output GEMM  Z[8192,768] @ Wo[768,768] --------------
__global__ void __launch_bounds__(256) out_gemm_kernel(const float* __restrict__ W,
                                                       const float* __restrict__ Bo,
                                                       float* __restrict__ out) {
    __shared__ float As[16][68];
    __shared__ float Bs[16][64];
    int tx = threadIdx.x & 15, ty = threadIdx.x >> 4;
    int m0 = blockIdx.y * 64, c0 = blockIdx.x * 64;
    float acc[4][4] = {};
    for (int k0 = 0; k0 < 768; k0 += 16) {
        #pragma unroll
        for (int it = 0; it < 4; it++) {
            int idx = threadIdx.x + it * 256;
            int m = idx >> 4, kk = idx & 15;
            As[kk][m] = g_z[(m0 + m) * 768 + k0 + kk];
        }
        #pragma unroll
        for (int it = 0; it < 4; it++) {
            int idx = threadIdx.x + it * 256;
            int kk = idx >> 6, c = idx & 63;
            Bs[kk][c] = W[(k0 + kk) * 768 + c0 + c];
        }
        __syncthreads();
        #pragma unroll
        for (int kk = 0; kk < 16; kk++) {
            float4 a4 = *(const float4*)&As[kk][ty * 4];
            float4 b4 = *(const float4*)&Bs[kk][tx * 4];
            float av[4] = {a4.x, a4.y, a4.z, a4.w};
            float bv[4] = {b4.x, b4.y, b4.z, b4.w};
            #pragma unroll
            for (int ri = 0; ri < 4; ri++)
                #pragma unroll
                for (int ci = 0; ci < 4; ci++)
                    acc[ri][ci] += av[ri] * bv[ci];
        }
        __syncthreads();
    }
    #pragma unroll
    for (int ri = 0; ri < 4; ri++) {
        int m = m0 + ty * 4 + ri;
        #pragma unroll
        for (int ci = 0; ci < 4; ci++) {
            int c = c0 + tx * 4 + ci;
            out[m * 768 + c] = acc[ri][ci] + Bo[c];
        }
    }
}

// ---------------- Kernel B: path bias -------------------------------------------
// Block handles (b, half of i-range). lane = h so path_emb gathers are coalesced
// (rows cached in smem). Output transposed through smem so [b,h,i,:] writes are
// contiguous.
__global__ void __launch_bounds__(256) path_kernel(const int* __restrict__ traj,
                                                   const int* __restrict__ distv,
                                                   const float* __restrict__ pemb,
                                                   const float* __restrict__ ppw) {
    extern __shared__ float ps[];
    float* pe = ps;                  // 512*32
    float* stage = ps + VP * HH;     // 64*33
    int b = blockIdx.x >> 1;
    int i0 = (blockIdx.x & 1) * 32;
    int tid = threadIdx.x;
    for (int e = tid; e < VP * HH; e += 256) pe[e] = pemb[e];
    int w = tid >> 5, lane = tid & 31;
    float w0 = ppw[lane], w1 = ppw[32 + lane], w2 = ppw[64 + lane], w3 = ppw[96 + lane];
    __syncthreads();
    for (int ii = 0; ii < 32; ii++) {
        int i = i0 + ii;
        #pragma unroll
        for (int jj = 0; jj < 8; jj++) {
            int j = w * 8 + jj;
            int base = (((b * NN + i) * NN) + j) * 12;
            int myidx = (lane < 12) ? traj[base + lane] : 0;
            float acc = 0.f;
            #pragma unroll
            for (int t = 0; t < 12; t++) {
                int id = __shfl_sync(0xffffffffu, myidx, t);
                float wl = (t < 3) ? w0 : (t < 6) ? w1 : (t < 9) ? w2 : w3;
                acc += pe[id * 32 + lane] * wl;
            }
            float dn = fmaxf((float)distv[(b * NN + i) * NN + j], 1.f);
            stage[j * 33 + lane] = acc / dn;
        }
        __syncthreads();
        for (int e = tid; e < HH * NN; e += 256) {
            int hh = e >> 6, j = e & 63;
            g_pb[(((b * HH + hh) * NN + i) << 6) + j] = stage[j * 33 + hh];
        }
        __syncthreads();
    }
}

// ---------------- Kernel C: attention per (b,h) ---------------------------------
struct AttnSmem {
    float q[NN*DK], k[NN*DK], v[NN*DK];
    float ektab[TE*DK], eqtab[TE*DK];   // edge_k_table (q side), edge_q_table (k side)
    float dktab[TD*DK], dqtab[TD*DK];
    float evtab[TE*DK], dvtab[TD*DK];
    float eqb[NN*TE];                   // q . ektab  [i][t]
    float dqb[NN*TD];                   // q . dktab  [i][t]
    float ekb_se[TE*NN];                // phase1-2: k . eqtab [t][j]; later s_e [i][t]
    float dkb_sd[TD*NN];                // phase1-2: k . dqtab [t][j]; later s_d [i][t]
    float amat[NN*NN];
    float trow[NN], tcol[NN];
    unsigned char ct[NN*NN], dt[NN*NN], maskv[NN];
};

__device__ __forceinline__ float dot24(const float* __restrict__ a, const float* __restrict__ b) {
    float s = 0.f;
    #pragma unroll
    for (int d = 0; d < 24; d++) s += a[d] * b[d];
    return s;
}

__global__ void __launch_bounds__(256) attn_kernel(const int* __restrict__ conn,
                                                   const int* __restrict__ distv,
                                                   const unsigned char* __restrict__ mask,
                                                   const float* __restrict__ Eq, const float* __restrict__ Ek,
                                                   const float* __restrict__ Dq, const float* __restrict__ Dk,
                                                   const float* __restrict__ Ev, const float* __restrict__ Dv,
                                                   const float* __restrict__ Tr, const float* __restrict__ Tc) {
    extern __shared__ char sraw[];
    AttnSmem& S = *reinterpret_cast<AttnSmem*>(sraw);
    int h = blockIdx.x, b = blockIdx.y;
    int tid = threadIdx.x;
    int qoff = (b * HH + h) * NN * DK;
    for (int e = tid; e < NN * DK; e += 256) {
        S.q[e] = g_q[qoff + e];
        S.k[e] = g_k[qoff + e];
        S.v[e] = g_v[qoff + e];
    }
    for (int e = tid; e < TE * DK; e += 256) {
        int t = e / 24, d = e % 24;
        S.ektab[e] = Ek[(t * HH + h) * DK + d];
        S.eqtab[e] = Eq[(t * HH + h) * DK + d];
        S.evtab[e] = Ev[(t * HH + h) * DK + d];
    }
    for (int e = tid; e < TD * DK; e += 256) {
        int t = e / 24, d = e % 24;
        S.dktab[e] = Dk[(t * HH + h) * DK + d];
        S.dqtab[e] = Dq[(t * HH + h) * DK + d];
        S.dvtab[e] = Dv[(t * HH + h) * DK + d];
    }
    if (tid < NN) {
        S.trow[tid] = Tr[h * NN + tid];
        S.tcol[tid] = Tc[h * NN + tid];
        S.maskv[tid] = mask[b * NN + tid];
    }
    int cdoff = b * NN * NN;
    int pboff = (b * HH + h) * NN * NN;
    for (int e = tid; e < NN * NN; e += 256) {
        S.ct[e] = (unsigned char)conn[cdoff + e];
        S.dt[e] = (unsigned char)distv[cdoff + e];
        S.amat[e] = g_pb[pboff + e];  // seed with path bias
    }
    __syncthreads();
    // phase 1: bias tables
    for (int e = tid; e < NN * TE; e += 256) { int i = e >> 5, t = e & 31; S.eqb[e] = dot24(S.q + i*24, S.ektab + t*24); }
    for (int e = tid; e < NN * TD; e += 256) { int i = e / 40, t = e % 40; S.dqb[e] = dot24(S.q + i*24, S.dktab + t*24); }
    for (int e = tid; e < TE * NN; e += 256) { int t = e >> 6, j = e & 63; S.ekb_se[e] = dot24(S.k + j*24, S.eqtab + t*24); }
    for (int e = tid; e < TD * NN; e += 256) { int t = e >> 6, j = e & 63; S.dkb_sd[e] = dot24(S.k + j*24, S.dqtab + t*24); }
    __syncthreads();
    // phase 2: assemble scores
    const float scale = 0.2041241452319315f;  // 24^-0.5
    for (int e = tid; e < NN * NN; e += 256) {
        int i = e >> 6, j = e & 63;
        float s = dot24(S.q + i*24, S.k + j*24);
        int c = S.ct[e], dd = S.dt[e];
        s += S.eqb[i*32 + c] + S.ekb_se[c*64 + j] + S.dqb[i*40 + dd] + S.dkb_sd[dd*64 + j] + S.amat[e];
        s *= scale;
        if (S.maskv[j]) s = -1e30f;
        S.amat[e] = s;
    }
    __syncthreads();
    // phase 3: zero the scatter bins (ekb/dkb dead now) + row softmax + toeplitz
    for (int e = tid; e < NN * TE; e += 256) S.ekb_se[e] = 0.f;
    for (int e = tid; e < NN * TD; e += 256) S.dkb_sd[e] = 0.f;
    {
        int w = tid >> 5, lane = tid & 31;
        #pragma unroll
        for (int r = 0; r < 8; r++) {
            int i = w * 8 + r;
            float a0 = S.amat[i*64 + lane], a1 = S.amat[i*64 + 32 + lane];
            float m = fmaxf(a0, a1);
            #pragma unroll
            for (int o = 16; o; o >>= 1) m = fmaxf(m, __shfl_xor_sync(0xffffffffu, m, o));
            float e0 = __expf(a0 - m), e1 = __expf(a1 - m);
            float ssum = e0 + e1;
            #pragma unroll
            for (int o = 16; o; o >>= 1) ssum += __shfl_xor_sync(0xffffffffu, ssum, o);
            float inv = 1.f / ssum;
            int j0 = lane, j1 = lane + 32;
            float t0 = (j0 >= i) ? S.trow[j0 - i] : S.tcol[i - j0];
            float t1 = (j1 >= i) ? S.trow[j1 - i] : S.tcol[i - j1];
            S.amat[i*64 + j0] = e0 * inv * t0;
            S.amat[i*64 + j1] = e1 * inv * t1;
        }
    }
    __syncthreads();
    // phase 4: type scatter into s_e / s_d
    for (int e = tid; e < NN * NN; e += 256) {
        int i = e >> 6;
        float a = S.amat[e];
        atomicAdd(&S.ekb_se[i*32 + S.ct[e]], a);
        atomicAdd(&S.dkb_sd[i*40 + S.dt[e]], a);
    }
    __syncthreads();
    // phase 5: z = a@v + s_e@Ev + s_d@Dv, write transposed [b, n, h*24+d]
    for (int e = tid; e < NN * DK; e += 256) {
        int i = e / 24, d = e % 24;
        float z = 0.f;
        const float* arow = S.amat + i * 64;
        #pragma unroll 8
        for (int j = 0; j < 64; j++) z += arow[j] * S.v[j*24 + d];
        const float* se = S.ekb_se + i * 32;
        #pragma unroll 8
        for (int t = 0; t < 32; t++) z += se[t] * S.evtab[t*24 + d];
        const float* sd = S.dkb_sd + i * 40;
        #pragma unroll 8
        for (int t = 0; t < 40; t++) z += sd[t] * S.dvtab[t*24 + d];
        g_z[(b * NN + i) * 768 + h * 24 + d] = z;
    }
}

// ---------------- launch --------------------------------------------------------
extern "C" void kernel_launch(void* const* d_in, const int* in_sizes, int n_in,
                              void* d_out, int out_size) {
    const float* node   = (const float*)d_in[0];
    const int*   distv  = (const int*)d_in[1];
    const int*   conn   = (const int*)d_in[2];
    const int*   traj   = (const int*)d_in[3];
    const unsigned char* mask = (const unsigned char*)d_in[4];
    const float* W_qkv  = (const float*)d_in[5];
    const float* b_qkv  = (const float*)d_in[6];
    const float* W_out  = (const float*)d_in[7];
    const float* b_out  = (const float*)d_in[8];
    const float* Eq     = (const float*)d_in[9];
    const float* Ek     = (const float*)d_in[10];
    const float* Dq     = (const float*)d_in[11];
    const float* Dk     = (const float*)d_in[12];
    const float* pemb   = (const float*)d_in[13];
    const float* ppw    = (const float*)d_in[14];
    const float* Ev     = (const float*)d_in[15];
    const float* Dv     = (const float*)d_in[16];
    const float* Tr     = (const float*)d_in[17];
    const float* Tc     = (const float*)d_in[18];
    float* out = (float*)d_out;

    int attn_smem = (int)sizeof(AttnSmem);
    int path_smem = (VP * HH + 64 * 33) * (int)sizeof(float);
    cudaFuncSetAttribute(attn_kernel, cudaFuncAttributeMaxDynamicSharedMemorySize, attn_smem);
    cudaFuncSetAttribute(path_kernel, cudaFuncAttributeMaxDynamicSharedMemorySize, path_smem);

    qkv_gemm_kernel<<<dim3(2304/64, 8192/64), 256>>>(node, W_qkv, b_qkv);
    path_kernel<<<BB * 2, 256, path_smem>>>(traj, distv, pemb, ppw);
    attn_kernel<<<dim3(HH, BB), 256, attn_smem>>>(conn, distv, mask,
                                                  Eq, Ek, Dq, Dk, Ev, Dv, Tr, Tc);
    out_gemm_kernel<<<dim3(768/64, 8192/64), 256>>>(W_out, b_out, out);
}

// round 2
// speedup vs baseline: 1.3279x; 1.3279x over previous
#include <cuda_runtime.h>
#include <cuda_bf16.h>
#include <math.h>
#include <cstdint>

// Problem constants
#define BB 128
#define NN 64
#define DD 768
#define HH 32
#define DK 24
#define LL 4
#define TE 32
#define TD 40
#define VP 512

// ---------------- scratch (device globals; no allocations allowed) -------------
__device__ float g_q[BB*HH*NN*DK];   // [b,h,n,d]
__device__ float g_k[BB*HH*NN*DK];
__device__ float g_v[BB*HH*NN*DK];
__device__ float g_pb[BB*HH*NN*NN];  // path bias [b,h,i,j]
__device__ float g_z[BB*NN*HH*DK];   // [b,n,h*dk]

// ---------------- tf32 warp-MMA helpers -----------------------------------------
__device__ __forceinline__ uint32_t f2tf32(float f) {
    uint32_t r;
    asm("cvt.rna.tf32.f32 %0, %1;" : "=r"(r) : "f"(f));
    return r;
}

__device__ __forceinline__ void mma_tf32(float* d, const uint32_t* a, const uint32_t* b) {
    asm volatile("mma.sync.aligned.m16n8k8.row.col.f32.tf32.tf32.f32 "
        "{%0,%1,%2,%3}, {%4,%5,%6,%7}, {%8,%9}, {%0,%1,%2,%3};"
        : "+f"(d[0]), "+f"(d[1]), "+f"(d[2]), "+f"(d[3])
        : "r"(a[0]), "r"(a[1]), "r"(a[2]), "r"(a[3]), "r"(b[0]), "r"(b[1]));
}

// ---------------- tensor-core GEMM: C[8192, NLD] = A[8192,768] @ W[768, NLD] ----
// CTA tile 128x128, 8 warps (2x4), warp tile 64x32, tf32 m16n8k8.
// QKV=true: scatter epilogue into g_q/g_k/g_v. QKV=false: A is g_z, plain store.
template<int NLD, bool QKV>
__global__ void __launch_bounds__(256) mma_gemm_kernel(const float* __restrict__ Ain,
                                                       const float* __restrict__ W,
                                                       const float* __restrict__ bias,
                                                       float* __restrict__ Cout) {
    __shared__ uint32_t As[128][33];
    __shared__ uint32_t Bs[128][33];
    const float* __restrict__ A = QKV ? Ain : (const float*)g_z;
    int tid = threadIdx.x;
    int wid = tid >> 5, lane = tid & 31;
    int group = lane >> 2, four = lane & 3;
    int wm = (wid >> 2) * 64, wn = (wid & 3) * 32;
    int m0 = blockIdx.y * 128, c0 = blockIdx.x * 128;
    float acc[4][4][4] = {};
    for (int k0 = 0; k0 < 768; k0 += 32) {
        #pragma unroll
        for (int it = 0; it < 4; it++) {
            int idx = it * 256 + tid;
            int row = idx >> 3, kv = (idx & 7) * 4;
            float4 v = *(const float4*)&A[(m0 + row) * 768 + k0 + kv];
            As[row][kv]     = f2tf32(v.x);
            As[row][kv + 1] = f2tf32(v.y);
            As[row][kv + 2] = f2tf32(v.z);
            As[row][kv + 3] = f2tf32(v.w);
        }
        #pragma unroll
        for (int it = 0; it < 4; it++) {
            int idx = it * 256 + tid;
            int kk = idx >> 5, nv = (idx & 31) * 4;
            float4 v = *(const float4*)&W[(k0 + kk) * NLD + c0 + nv];
            Bs[nv][kk]     = f2tf32(v.x);
            Bs[nv + 1][kk] = f2tf32(v.y);
            Bs[nv + 2][kk] = f2tf32(v.z);
            Bs[nv + 3][kk] = f2tf32(v.w);
        }
        __syncthreads();
        #pragma unroll
        for (int ks = 0; ks < 4; ks++) {
            int kk = ks * 8;
            uint32_t af[4][4], bf[4][2];
            #pragma unroll
            for (int fm = 0; fm < 4; fm++) {
                int r = wm + fm * 16 + group;
                af[fm][0] = As[r][kk + four];
                af[fm][1] = As[r + 8][kk + four];
                af[fm][2] = As[r][kk + four + 4];
                af[fm][3] = As[r + 8][kk + four + 4];
            }
            #pragma unroll
            for (int fn = 0; fn < 4; fn++) {
                int n = wn + fn * 8 + group;
                bf[fn][0] = Bs[n][kk + four];
                bf[fn][1] = Bs[n][kk + four + 4];
            }
            #pragma unroll
            for (int fm = 0; fm < 4; fm++)
                #pragma unroll
                for (int fn = 0; fn < 4; fn++)
                    mma_tf32(acc[fm][fn], af[fm], bf[fn]);
        }
        __syncthreads();
    }
    // epilogue
    #pragma unroll
    for (int fm = 0; fm < 4; fm++) {
        #pragma unroll
        for (int fn = 0; fn < 4; fn++) {
            #pragma unroll
            for (int r = 0; r < 4; r++) {
                int m = m0 + wm + fm * 16 + group + ((r >> 1) ? 8 : 0);
                int c = c0 + wn + fn * 8 + four * 2 + (r & 1);
                float val = acc[fm][fn][r] + bias[c];
                if (QKV) {
                    int b = m >> 6, n = m & 63;
                    int s = c / 768, rem = c - s * 768;
                    int h = rem / 24, d = rem % 24;
                    float* dst = (s == 0) ? g_q : (s == 1) ? g_k : g_v;
                    dst[((b * HH + h) * NN + n) * DK + d] = val;
                } else {
                    Cout[m * 768 + c] = val;
                }
            }
        }
    }
}

// ---------------- Kernel B: path bias -------------------------------------------
__global__ void __launch_bounds__(256) path_kernel(const int* __restrict__ traj,
                                                   const int* __restrict__ distv,
                                                   const float* __restrict__ pemb,
                                                   const float* __restrict__ ppw) {
    extern __shared__ float ps[];
    float* pe = ps;                  // 512*32
    float* stage = ps + VP * HH;     // 64*33
    int b = blockIdx.x >> 1;
    int i0 = (blockIdx.x & 1) * 32;
    int tid = threadIdx.x;
    for (int e = tid; e < VP * HH; e += 256) pe[e] = pemb[e];
    int w = tid >> 5, lane = tid & 31;
    float w0 = ppw[lane], w1 = ppw[32 + lane], w2 = ppw[64 + lane], w3 = ppw[96 + lane];
    __syncthreads();
    for (int ii = 0; ii < 32; ii++) {
        int i = i0 + ii;
        #pragma unroll
        for (int jj = 0; jj < 8; jj++) {
            int j = w * 8 + jj;
            int base = (((b * NN + i) * NN) + j) * 12;
            int myidx = (lane < 12) ? traj[base + lane] : 0;
            float acc = 0.f;
            #pragma unroll
            for (int t = 0; t < 12; t++) {
                int id = __shfl_sync(0xffffffffu, myidx, t);
                float wl = (t < 3) ? w0 : (t < 6) ? w1 : (t < 9) ? w2 : w3;
                acc += pe[id * 32 + lane] * wl;
            }
            float dn = fmaxf((float)distv[(b * NN + i) * NN + j], 1.f);
            stage[j * 33 + lane] = acc / dn;
        }
        __syncthreads();
        for (int e = tid; e < HH * NN; e += 256) {
            int hh = e >> 6, j = e & 63;
            g_pb[(((b * HH + hh) * NN + i) << 6) + j] = stage[j * 33 + hh];
        }
        __syncthreads();
    }
}

// ---------------- Kernel C: attention per (b,h) ---------------------------------
struct AttnSmem {
    float q[NN*DK], k[NN*DK], v[NN*DK];
    float ektab[TE*DK], eqtab[TE*DK];
    float dktab[TD*DK], dqtab[TD*DK];
    float evtab[TE*DK], dvtab[TD*DK];
    float eqb[NN*TE];                   // q . ektab  [i][t]
    float dqb[NN*TD];                   // q . dktab  [i][t]
    float ekb_se[TE*NN];                // phase1-2: k . eqtab [t][j]; later s_e [i][t]
    float dkb_sd[TD*NN];                // phase1-2: k . dqtab [t][j]; later s_d [i][t]
    float amat[NN*NN];
    float trow[NN], tcol[NN];
    unsigned char ct[NN*NN], dt[NN*NN], maskv[NN];
};

__device__ __forceinline__ float dot24(const float* __restrict__ a, const float* __restrict__ b) {
    float s = 0.f;
    #pragma unroll
    for (int d = 0; d < 24; d++) s += a[d] * b[d];
    return s;
}

__global__ void __launch_bounds__(256) attn_kernel(const int* __restrict__ conn,
                                                   const int* __restrict__ distv,
                                                   const unsigned char* __restrict__ mask,
                                                   const float* __restrict__ Eq, const float* __restrict__ Ek,
                                                   const float* __restrict__ Dq, const float* __restrict__ Dk,
                                                   const float* __restrict__ Ev, const float* __restrict__ Dv,
                                                   const float* __restrict__ Tr, const float* __restrict__ Tc) {
    extern __shared__ char sraw[];
    AttnSmem& S = *reinterpret_cast<AttnSmem*>(sraw);
    int h = blockIdx.x, b = blockIdx.y;
    int tid = threadIdx.x;
    int qoff = (b * HH + h) * NN * DK;
    for (int e = tid; e < NN * DK; e += 256) {
        S.q[e] = g_q[qoff + e];
        S.k[e] = g_k[qoff + e];
        S.v[e] = g_v[qoff + e];
    }
    for (int e = tid; e < TE * DK; e += 256) {
        int t = e / 24, d = e % 24;
        S.ektab[e] = Ek[(t * HH + h) * DK + d];
        S.eqtab[e] = Eq[(t * HH + h) * DK + d];
        S.evtab[e] = Ev[(t * HH + h) * DK + d];
    }
    for (int e = tid; e < TD * DK; e += 256) {
        int t = e / 24, d = e % 24;
        S.dktab[e] = Dk[(t * HH + h) * DK + d];
        S.dqtab[e] = Dq[(t * HH + h) * DK + d];
        S.dvtab[e] = Dv[(t * HH + h) * DK + d];
    }
    if (tid < NN) {
        S.trow[tid] = Tr[h * NN + tid];
        S.tcol[tid] = Tc[h * NN + tid];
        S.maskv[tid] = mask[b * NN + tid];
    }
    int cdoff = b * NN * NN;
    int pboff = (b * HH + h) * NN * NN;
    for (int e = tid; e < NN * NN; e += 256) {
        S.ct[e] = (unsigned char)conn[cdoff + e];
        S.dt[e] = (unsigned char)distv[cdoff + e];
        S.amat[e] = g_pb[pboff + e];
    }
    __syncthreads();
    // phase 1: bias tables
    for (int e = tid; e < NN * TE; e += 256) { int i = e >> 5, t = e & 31; S.eqb[e] = dot24(S.q + i*24, S.ektab + t*24); }
    for (int e = tid; e < NN * TD; e += 256) { int i = e / 40, t = e % 40; S.dqb[e] = dot24(S.q + i*24, S.dktab + t*24); }
    for (int e = tid; e < TE * NN; e += 256) { int t = e >> 6, j = e & 63; S.ekb_se[e] = dot24(S.k + j*24, S.eqtab + t*24); }
    for (int e = tid; e < TD * NN; e += 256) { int t = e >> 6, j = e & 63; S.dkb_sd[e] = dot24(S.k + j*24, S.dqtab + t*24); }
    __syncthreads();
    // phase 2: assemble scores
    const float scale = 0.2041241452319315f;  // 24^-0.5
    for (int e = tid; e < NN * NN; e += 256) {
        int i = e >> 6, j = e & 63;
        float s = dot24(S.q + i*24, S.k + j*24);
        int c = S.ct[e], dd = S.dt[e];
        s += S.eqb[i*32 + c] + S.ekb_se[c*64 + j] + S.dqb[i*40 + dd] + S.dkb_sd[dd*64 + j] + S.amat[e];
        s *= scale;
        if (S.maskv[j]) s = -1e30f;
        S.amat[e] = s;
    }
    __syncthreads();
    // phase 3: zero scatter bins + row softmax + toeplitz
    for (int e = tid; e < NN * TE; e += 256) S.ekb_se[e] = 0.f;
    for (int e = tid; e < NN * TD; e += 256) S.dkb_sd[e] = 0.f;
    {
        int w = tid >> 5, lane = tid & 31;
        #pragma unroll
        for (int r = 0; r < 8; r++) {
            int i = w * 8 + r;
            float a0 = S.amat[i*64 + lane], a1 = S.amat[i*64 + 32 + lane];
            float m = fmaxf(a0, a1);
            #pragma unroll
            for (int o = 16; o; o >>= 1) m = fmaxf(m, __shfl_xor_sync(0xffffffffu, m, o));
            float e0 = __expf(a0 - m), e1 = __expf(a1 - m);
            float ssum = e0 + e1;
            #pragma unroll
            for (int o = 16; o; o >>= 1) ssum += __shfl_xor_sync(0xffffffffu, ssum, o);
            float inv = 1.f / ssum;
            int j0 = lane, j1 = lane + 32;
            float t0 = (j0 >= i) ? S.trow[j0 - i] : S.tcol[i - j0];
            float t1 = (j1 >= i) ? S.trow[j1 - i] : S.tcol[i - j1];
            S.amat[i*64 + j0] = e0 * inv * t0;
            S.amat[i*64 + j1] = e1 * inv * t1;
        }
    }
    __syncthreads();
    // phase 4: type scatter into s_e / s_d
    for (int e = tid; e < NN * NN; e += 256) {
        int i = e >> 6;
        float a = S.amat[e];
        atomicAdd(&S.ekb_se[i*32 + S.ct[e]], a);
        atomicAdd(&S.dkb_sd[i*40 + S.dt[e]], a);
    }
    __syncthreads();
    // phase 5: z = a@v + s_e@Ev + s_d@Dv, write transposed [b, n, h*24+d]
    for (int e = tid; e < NN * DK; e += 256) {
        int i = e / 24, d = e % 24;
        float z = 0.f;
        const float* arow = S.amat + i * 64;
        #pragma unroll 8
        for (int j = 0; j < 64; j++) z += arow[j] * S.v[j*24 + d];
        const float* se = S.ekb_se + i * 32;
        #pragma unroll 8
        for (int t = 0; t < 32; t++) z += se[t] * S.evtab[t*24 + d];
        const float* sd = S.dkb_sd + i * 40;
        #pragma unroll 8
        for (int t = 0; t < 40; t++) z += sd[t] * S.dvtab[t*24 + d];
        g_z[(b * NN + i) * 768 + h * 24 + d] = z;
    }
}

// ---------------- launch --------------------------------------------------------
extern "C" void kernel_launch(void* const* d_in, const int* in_sizes, int n_in,
                              void* d_out, int out_size) {
    const float* node   = (const float*)d_in[0];
    const int*   distv  = (const int*)d_in[1];
    const int*   conn   = (const int*)d_in[2];
    const int*   traj   = (const int*)d_in[3];
    const unsigned char* mask = (const unsigned char*)d_in[4];
    const float* W_qkv  = (const float*)d_in[5];
    const float* b_qkv  = (const float*)d_in[6];
    const float* W_out  = (const float*)d_in[7];
    const float* b_out  = (const float*)d_in[8];
    const float* Eq     = (const float*)d_in[9];
    const float* Ek     = (const float*)d_in[10];
    const float* Dq     = (const float*)d_in[11];
    const float* Dk     = (const float*)d_in[12];
    const float* pemb   = (const float*)d_in[13];
    const float* ppw    = (const float*)d_in[14];
    const float* Ev     = (const float*)d_in[15];
    const float* Dv     = (const float*)d_in[16];
    const float* Tr     = (const float*)d_in[17];
    const float* Tc     = (const float*)d_in[18];
    float* out = (float*)d_out;

    int attn_smem = (int)sizeof(AttnSmem);
    int path_smem = (VP * HH + 64 * 33) * (int)sizeof(float);
    cudaFuncSetAttribute(attn_kernel, cudaFuncAttributeMaxDynamicSharedMemorySize, attn_smem);
    cudaFuncSetAttribute(path_kernel, cudaFuncAttributeMaxDynamicSharedMemorySize, path_smem);

    mma_gemm_kernel<2304, true><<<dim3(2304/128, 8192/128), 256>>>(node, W_qkv, b_qkv, nullptr);
    path_kernel<<<BB * 2, 256, path_smem>>>(traj, distv, pemb, ppw);
    attn_kernel<<<dim3(HH, BB), 256, attn_smem>>>(conn, distv, mask,
                                                  Eq, Ek, Dq, Dk, Ev, Dv, Tr, Tc);
    mma_gemm_kernel<768, false><<<dim3(768/128, 8192/128), 256>>>(nullptr, W_out, b_out, out);
}